// round 13
// baseline (speedup 1.0000x reference)
#include <cuda_runtime.h>
#include <cuda_bf16.h>
#include <cstdint>

// Problem constants (fixed by the dataset)
#define B_DIM   16
#define N_DIM   50000          // even
#define E_DIM   1600000
#define BN      (B_DIM * N_DIM)
#define CLAMP_MIN_F (-10.0f)
#define CLAMP_MAX_F ( 10.0f)
#define EPS_F   (1e-6f)

// Transposed (N, B) scratch: each node's 16 batch values are contiguous (64B).
__device__ float g_ET [N_DIM * B_DIM];   // E transposed
__device__ float g_OT [N_DIM * B_DIM];   // o_pre transposed
__device__ float g_ACC[N_DIM * B_DIM];   // accumulator, init to E + chem

// ---------------------------------------------------------------------------
// Kernel A: transpose + init accumulator; smem-staged, float2-granular.
// 256-thread blocks, 32 nodes/block, grid 1563 -> 400k threads (84 warps/SM:
// occupancy ceiling lifted from 66% to 100% vs the float4 versions).
// Phase 1: t -> (b = t>>4, n2 = t&15): dense float2 LDG (16 lanes cover 128B
//   per b-row). Stage to smem.
// Phase 2: t -> (ni = t>>3, p = t&7): dense float2 STG (8 lanes emit one
//   node's contiguous 64B; warp covers 256B runs).
// ---------------------------------------------------------------------------
__global__ void __launch_bounds__(256)
prep_kernel(const float* __restrict__ chem,
            const float* __restrict__ E,
            const float* __restrict__ o_pre)
{
    __shared__ float s_e[B_DIM][33];   // b-major rows of 32 nodes (+1 pad)
    __shared__ float s_o[B_DIM][33];
    __shared__ float s_a[B_DIM][33];

    const int n0 = blockIdx.x * 32;
    const int t  = threadIdx.x;

    // Phase 1: dense float2 loads (b-major within the block).
    {
        int b  = t >> 4;           // 0..15
        int n2 = t & 15;           // node pair within block
        int n  = n0 + n2 * 2;
        if (n < N_DIM) {           // N even -> pairs never split
            float2 e = __ldg(reinterpret_cast<const float2*>(&E    [b * N_DIM + n]));
            float2 o = __ldg(reinterpret_cast<const float2*>(&o_pre[b * N_DIM + n]));
            float2 c = __ldg(reinterpret_cast<const float2*>(&chem [b * N_DIM + n]));
            s_e[b][n2*2]   = e.x;  s_e[b][n2*2+1] = e.y;
            s_o[b][n2*2]   = o.x;  s_o[b][n2*2+1] = o.y;
            s_a[b][n2*2]   = e.x + c.x;  s_a[b][n2*2+1] = e.y + c.y;
        }
    }
    __syncthreads();

    // Phase 2: dense float2 stores (node-major).
    {
        int ni = t >> 3;           // 0..31 local node
        int p  = t & 7;            // batch pair (b0 = 2p)
        int n  = n0 + ni;
        if (n < N_DIM) {
            int b0 = p * 2;
            float2 ve = make_float2(s_e[b0][ni], s_e[b0+1][ni]);
            float2 vo = make_float2(s_o[b0][ni], s_o[b0+1][ni]);
            float2 va = make_float2(s_a[b0][ni], s_a[b0+1][ni]);
            int base = n * B_DIM + b0;
            *reinterpret_cast<float2*>(&g_ET [base]) = ve;
            *reinterpret_cast<float2*>(&g_OT [base]) = vo;
            *reinterpret_cast<float2*>(&g_ACC[base]) = va;
        }
    }
}

// ---------------------------------------------------------------------------
// Kernel B: edge scatter (byte-identical to R11; ~91% of LTS cap — protected).
// 4 lanes per edge; each lane owns one batch quad (float4). Quad lanes load
// contiguous 16B pieces of the edge's 64B block (one 64B request per quad).
// red.global.add.v4.f32 -> no-return L2-side add, one RED.128 per lane.
// ---------------------------------------------------------------------------
__global__ void __launch_bounds__(256)
edge_kernel(const float* __restrict__ w,
            const int*   __restrict__ src,
            const int*   __restrict__ dst)
{
    int t = blockIdx.x * blockDim.x + threadIdx.x;
    if (t >= E_DIM * 4) return;
    int e = t >> 2;
    int q = t & 3;

    int   s  = __ldg(&src[e]);
    int   d  = __ldg(&dst[e]);
    float wv = __ldg(&w[e]);

    const float4 Oj = __ldg(reinterpret_cast<const float4*>(&g_OT[s * B_DIM + q * 4]));
    const float4 En = __ldg(reinterpret_cast<const float4*>(&g_ET[d * B_DIM + q * 4]));

    float4 c;
    c.x = (Oj.x >= En.x) ? (Oj.x * wv) : (-Oj.x * wv);
    c.y = (Oj.y >= En.y) ? (Oj.y * wv) : (-Oj.y * wv);
    c.z = (Oj.z >= En.z) ? (Oj.z * wv) : (-Oj.z * wv);
    c.w = (Oj.w >= En.w) ? (Oj.w * wv) : (-Oj.w * wv);

    float* p = &g_ACC[d * B_DIM + q * 4];
    asm volatile("red.global.add.v4.f32 [%0], {%1, %2, %3, %4};"
                 :: "l"(p), "f"(c.x), "f"(c.y), "f"(c.z), "f"(c.w)
                 : "memory");
}

// ---------------------------------------------------------------------------
// Kernel C: epilogue; smem-staged, float2-granular (mirror of prep).
// Phase 1: t -> (ni = t>>3, p = t&7): dense float2 loads of ACC and ET
//   (64B per node across 8 lanes), epilogue math on 2 elements, stage.
// Phase 2: t -> (b = t>>4, n2 = t&15): dense float2 stores of both planes.
// ---------------------------------------------------------------------------
__global__ void __launch_bounds__(256)
final_kernel(const float* __restrict__ threshold,
             const float* __restrict__ decay,
             float* __restrict__ out)
{
    __shared__ float s_no[B_DIM][33];
    __shared__ float s_ne[B_DIM][33];

    const int n0 = blockIdx.x * 32;
    const int t  = threadIdx.x;

    // Phase 1: dense float2 loads + epilogue math.
    {
        int ni = t >> 3;           // 0..31
        int p  = t & 7;            // batch pair
        int n  = n0 + ni;
        if (n < N_DIM) {
            int b0   = p * 2;
            int base = n * B_DIM + b0;
            float2 Sv = *reinterpret_cast<const float2*>(&g_ACC[base]);
            float2 Ev = *reinterpret_cast<const float2*>(&g_ET [base]);
            float thr = __ldg(&threshold[n]);   // broadcast across 8 lanes
            float dec = __ldg(&decay[n]);

            float Sa[2] = {Sv.x, Sv.y};
            float Ea[2] = {Ev.x, Ev.y};
            #pragma unroll
            for (int j = 0; j < 2; j++) {
                int b = b0 + j;
                float S  = fminf(fmaxf(Sa[j], CLAMP_MIN_F), CLAMP_MAX_F);
                float ev = Ea[j];
                bool  gt    = S > thr;
                float new_o = fmaxf(S - thr, 0.0f);
                bool  mask  = (!gt) && (fabsf(S - ev) <= EPS_F);
                float new_e = gt ? new_o : (mask ? (ev - dec) : S);
                s_no[b][ni] = new_o;
                s_ne[b][ni] = new_e;
            }
        }
    }
    __syncthreads();

    // Phase 2: dense float2 stores (b-major).
    {
        int b  = t >> 4;           // 0..15
        int n2 = t & 15;           // node pair
        int n  = n0 + n2 * 2;
        if (n < N_DIM) {
            float2 o2 = make_float2(s_no[b][n2*2], s_no[b][n2*2+1]);
            float2 e2 = make_float2(s_ne[b][n2*2], s_ne[b][n2*2+1]);
            *reinterpret_cast<float2*>(&out[b * N_DIM + n])      = o2;
            *reinterpret_cast<float2*>(&out[BN + b * N_DIM + n]) = e2;
        }
    }
}

// ---------------------------------------------------------------------------
// Launch. Inputs (metadata order):
//   0 chem_influence (B,N) f32   1 E (B,N) f32       2 o_pre (B,N) f32
//   3 w (E,) f32                 4 threshold (N,) f32 5 decay (N,) f32
//   6 src (E,) i32               7 dst (E,) i32
// Output: new_o (B,N) then new_e (B,N) concatenated, f32.
// ---------------------------------------------------------------------------
extern "C" void kernel_launch(void* const* d_in, const int* in_sizes, int n_in,
                              void* d_out, int out_size)
{
    const float* chem  = (const float*)d_in[0];
    const float* E     = (const float*)d_in[1];
    const float* o_pre = (const float*)d_in[2];
    const float* w     = (const float*)d_in[3];
    const float* thr   = (const float*)d_in[4];
    const float* dec   = (const float*)d_in[5];
    const int*   src   = (const int*)  d_in[6];
    const int*   dst   = (const int*)  d_in[7];
    float* out = (float*)d_out;

    int node_blocks = (N_DIM + 31) / 32;                // 1563
    int edge_blocks = (E_DIM * 4 + 255) / 256;          // 25000

    prep_kernel <<<node_blocks, 256>>>(chem, E, o_pre);
    edge_kernel <<<edge_blocks, 256>>>(w, src, dst);
    final_kernel<<<node_blocks, 256>>>(thr, dec, out);
}

// round 14
// speedup vs baseline: 1.0299x; 1.0299x over previous
#include <cuda_runtime.h>
#include <cuda_bf16.h>
#include <cstdint>

// Problem constants (fixed by the dataset)
#define B_DIM   16
#define N_DIM   50000          // divisible by 4
#define E_DIM   1600000
#define BN      (B_DIM * N_DIM)
#define CLAMP_MIN_F (-10.0f)
#define CLAMP_MAX_F ( 10.0f)
#define EPS_F   (1e-6f)

// Transposed (N, B) scratch: each node's 16 batch values are contiguous (64B).
__device__ float g_ET [N_DIM * B_DIM];   // E transposed
__device__ float g_OT [N_DIM * B_DIM];   // o_pre transposed
__device__ float g_ACC[N_DIM * B_DIM];   // accumulator, init to E + chem

// ---------------------------------------------------------------------------
// Kernel A: transpose + init accumulator (R11's winning shape, byte-identical
// data path). Block = 64 nodes, 256 threads.
// ---------------------------------------------------------------------------
__global__ void __launch_bounds__(256)
prep_kernel(const float* __restrict__ chem,
            const float* __restrict__ E,
            const float* __restrict__ o_pre)
{
    __shared__ float4 s_e[B_DIM][17];   // rows padded: 17 float4 = 68 floats
    __shared__ float4 s_o[B_DIM][17];
    __shared__ float4 s_a[B_DIM][17];

    const int n0 = blockIdx.x * 64;
    const int t  = threadIdx.x;

    // Phase 1: dense float4 loads (b-major within the block).
    {
        int b  = t >> 4;           // 0..15
        int n4 = t & 15;           // 0..15 (node quad within block)
        int n  = n0 + n4 * 4;
        if (n < N_DIM) {
            float4 e = __ldg(reinterpret_cast<const float4*>(&E    [b * N_DIM + n]));
            float4 o = __ldg(reinterpret_cast<const float4*>(&o_pre[b * N_DIM + n]));
            float4 c = __ldg(reinterpret_cast<const float4*>(&chem [b * N_DIM + n]));
            s_e[b][n4] = e;
            s_o[b][n4] = o;
            s_a[b][n4] = make_float4(e.x + c.x, e.y + c.y, e.z + c.z, e.w + c.w);
        }
    }
    __syncthreads();

    // Phase 2: dense float4 stores (node-major).
    {
        int ni = t >> 2;           // 0..63 local node
        int qq = t & 3;            // batch quad
        int n  = n0 + ni;
        if (n < N_DIM) {
            const float* ef = reinterpret_cast<const float*>(s_e);
            const float* of = reinterpret_cast<const float*>(s_o);
            const float* af = reinterpret_cast<const float*>(s_a);
            int b0 = qq * 4;
            float4 ve = make_float4(ef[(b0+0)*68 + ni], ef[(b0+1)*68 + ni],
                                    ef[(b0+2)*68 + ni], ef[(b0+3)*68 + ni]);
            float4 vo = make_float4(of[(b0+0)*68 + ni], of[(b0+1)*68 + ni],
                                    of[(b0+2)*68 + ni], of[(b0+3)*68 + ni]);
            float4 va = make_float4(af[(b0+0)*68 + ni], af[(b0+1)*68 + ni],
                                    af[(b0+2)*68 + ni], af[(b0+3)*68 + ni]);
            int base = n * B_DIM + b0;
            *reinterpret_cast<float4*>(&g_ET [base]) = ve;
            *reinterpret_cast<float4*>(&g_OT [base]) = vo;
            *reinterpret_cast<float4*>(&g_ACC[base]) = va;
        }
    }
    // Let the dependent edge kernel launch as soon as we're winding down.
    cudaTriggerProgrammaticLaunchCompletion();
}

// ---------------------------------------------------------------------------
// Kernel B: edge scatter (R11 data path) + PDL split: index loads (src/dst/w,
// independent of prep) issue BEFORE cudaGridDependencySynchronize(); the
// OT/ET gathers and the RED wait until prep's writes are visible.
// ---------------------------------------------------------------------------
__global__ void __launch_bounds__(256)
edge_kernel(const float* __restrict__ w,
            const int*   __restrict__ src,
            const int*   __restrict__ dst)
{
    int t = blockIdx.x * blockDim.x + threadIdx.x;

    int s = 0, d = 0;
    float wv = 0.0f;
    bool active = (t < E_DIM * 4);
    int e = t >> 2;
    int q = t & 3;
    if (active) {
        s  = __ldg(&src[e]);
        d  = __ldg(&dst[e]);
        wv = __ldg(&w[e]);
    }

    // Wait for prep's grid to complete (memory visible) before gathers.
    cudaGridDependencySynchronize();

    if (active) {
        const float4 Oj = __ldg(reinterpret_cast<const float4*>(&g_OT[s * B_DIM + q * 4]));
        const float4 En = __ldg(reinterpret_cast<const float4*>(&g_ET[d * B_DIM + q * 4]));

        float4 c;
        c.x = (Oj.x >= En.x) ? (Oj.x * wv) : (-Oj.x * wv);
        c.y = (Oj.y >= En.y) ? (Oj.y * wv) : (-Oj.y * wv);
        c.z = (Oj.z >= En.z) ? (Oj.z * wv) : (-Oj.z * wv);
        c.w = (Oj.w >= En.w) ? (Oj.w * wv) : (-Oj.w * wv);

        float* p = &g_ACC[d * B_DIM + q * 4];
        asm volatile("red.global.add.v4.f32 [%0], {%1, %2, %3, %4};"
                     :: "l"(p), "f"(c.x), "f"(c.y), "f"(c.z), "f"(c.w)
                     : "memory");
    }
    cudaTriggerProgrammaticLaunchCompletion();
}

// ---------------------------------------------------------------------------
// Kernel C: epilogue (R11 data path) + PDL: threshold/decay prefetch before
// the dependency sync; ACC/ET reads after.
// ---------------------------------------------------------------------------
__global__ void __launch_bounds__(256)
final_kernel(const float* __restrict__ threshold,
             const float* __restrict__ decay,
             float* __restrict__ out)
{
    __shared__ float4 s_no[B_DIM][17];
    __shared__ float4 s_ne[B_DIM][17];

    const int n0 = blockIdx.x * 64;
    const int t  = threadIdx.x;

    int ni = t >> 2;
    int qq = t & 3;
    int n  = n0 + ni;
    float thr = 0.0f, dec = 0.0f;
    bool act = (n < N_DIM);
    if (act) {
        thr = __ldg(&threshold[n]);   // independent of the edge kernel
        dec = __ldg(&decay[n]);
    }

    cudaGridDependencySynchronize();

    // Phase 1: dense loads + epilogue math.
    if (act) {
        int base = n * B_DIM + qq * 4;
        float4 Sv = *reinterpret_cast<const float4*>(&g_ACC[base]);
        float4 Ev = *reinterpret_cast<const float4*>(&g_ET [base]);

        float* nof = reinterpret_cast<float*>(s_no);
        float* nef = reinterpret_cast<float*>(s_ne);
        float Sa[4] = {Sv.x, Sv.y, Sv.z, Sv.w};
        float Ea[4] = {Ev.x, Ev.y, Ev.z, Ev.w};
        #pragma unroll
        for (int j = 0; j < 4; j++) {
            int b = qq * 4 + j;
            float S  = fminf(fmaxf(Sa[j], CLAMP_MIN_F), CLAMP_MAX_F);
            float ev = Ea[j];
            bool  gt    = S > thr;
            float new_o = fmaxf(S - thr, 0.0f);
            bool  mask  = (!gt) && (fabsf(S - ev) <= EPS_F);
            float new_e = gt ? new_o : (mask ? (ev - dec) : S);
            nof[b * 68 + ni] = new_o;
            nef[b * 68 + ni] = new_e;
        }
    }
    __syncthreads();

    // Phase 2: dense float4 stores (b-major).
    {
        int b  = t >> 4;           // 0..15
        int n4 = t & 15;           // node quad
        int nn = n0 + n4 * 4;
        if (nn < N_DIM) {
            *reinterpret_cast<float4*>(&out[b * N_DIM + nn])      = s_no[b][n4];
            *reinterpret_cast<float4*>(&out[BN + b * N_DIM + nn]) = s_ne[b][n4];
        }
    }
}

// ---------------------------------------------------------------------------
// Launch. Inputs (metadata order):
//   0 chem_influence (B,N) f32   1 E (B,N) f32       2 o_pre (B,N) f32
//   3 w (E,) f32                 4 threshold (N,) f32 5 decay (N,) f32
//   6 src (E,) i32               7 dst (E,) i32
// Output: new_o (B,N) then new_e (B,N) concatenated, f32.
// PDL: edge and final launch with programmaticStreamSerialization so their
// prologues overlap the predecessor's tail. Graph-capturable.
// ---------------------------------------------------------------------------
extern "C" void kernel_launch(void* const* d_in, const int* in_sizes, int n_in,
                              void* d_out, int out_size)
{
    const float* chem  = (const float*)d_in[0];
    const float* E     = (const float*)d_in[1];
    const float* o_pre = (const float*)d_in[2];
    const float* w     = (const float*)d_in[3];
    const float* thr   = (const float*)d_in[4];
    const float* dec   = (const float*)d_in[5];
    const int*   src   = (const int*)  d_in[6];
    const int*   dst   = (const int*)  d_in[7];
    float* out = (float*)d_out;

    int node_blocks = (N_DIM + 63) / 64;                // 782
    int edge_blocks = (E_DIM * 4 + 255) / 256;          // 25000

    prep_kernel<<<node_blocks, 256>>>(chem, E, o_pre);

    cudaLaunchAttribute pdl[1];
    pdl[0].id = cudaLaunchAttributeProgrammaticStreamSerialization;
    pdl[0].val.programmaticStreamSerializationAllowed = 1;

    {
        cudaLaunchConfig_t cfg = {};
        cfg.gridDim  = dim3(edge_blocks, 1, 1);
        cfg.blockDim = dim3(256, 1, 1);
        cfg.attrs    = pdl;
        cfg.numAttrs = 1;
        cudaLaunchKernelEx(&cfg, edge_kernel, w, src, dst);
    }
    {
        cudaLaunchConfig_t cfg = {};
        cfg.gridDim  = dim3(node_blocks, 1, 1);
        cfg.blockDim = dim3(256, 1, 1);
        cfg.attrs    = pdl;
        cfg.numAttrs = 1;
        cudaLaunchKernelEx(&cfg, final_kernel, thr, dec, out);
    }
}

// round 15
// speedup vs baseline: 1.0374x; 1.0073x over previous
#include <cuda_runtime.h>
#include <cuda_bf16.h>
#include <cstdint>

// Problem constants (fixed by the dataset)
#define B_DIM   16
#define N_DIM   50000          // divisible by 4
#define E_DIM   1600000
#define BN      (B_DIM * N_DIM)
#define CLAMP_MIN_F (-10.0f)
#define CLAMP_MAX_F ( 10.0f)
#define EPS_F   (1e-6f)

// Transposed (N, B) scratch: each node's 16 batch values are contiguous (64B).
__device__ float g_ET [N_DIM * B_DIM];   // E transposed
__device__ float g_OT [N_DIM * B_DIM];   // o_pre transposed
__device__ float g_ACC[N_DIM * B_DIM];   // accumulator, init to E + chem

// ---------------------------------------------------------------------------
// Kernel A: transpose + init accumulator (R11's winning shape, unchanged).
// Block = 64 nodes, 256 threads; smem-staged, dense float4 on both sides.
// Plain launch: no PDL consumer racing it for SM slots.
// ---------------------------------------------------------------------------
__global__ void __launch_bounds__(256)
prep_kernel(const float* __restrict__ chem,
            const float* __restrict__ E,
            const float* __restrict__ o_pre)
{
    __shared__ float4 s_e[B_DIM][17];   // rows padded: 17 float4 = 68 floats
    __shared__ float4 s_o[B_DIM][17];
    __shared__ float4 s_a[B_DIM][17];

    const int n0 = blockIdx.x * 64;
    const int t  = threadIdx.x;

    // Phase 1: dense float4 loads (b-major within the block).
    {
        int b  = t >> 4;           // 0..15
        int n4 = t & 15;           // 0..15 (node quad within block)
        int n  = n0 + n4 * 4;
        if (n < N_DIM) {
            float4 e = __ldg(reinterpret_cast<const float4*>(&E    [b * N_DIM + n]));
            float4 o = __ldg(reinterpret_cast<const float4*>(&o_pre[b * N_DIM + n]));
            float4 c = __ldg(reinterpret_cast<const float4*>(&chem [b * N_DIM + n]));
            s_e[b][n4] = e;
            s_o[b][n4] = o;
            s_a[b][n4] = make_float4(e.x + c.x, e.y + c.y, e.z + c.z, e.w + c.w);
        }
    }
    __syncthreads();

    // Phase 2: dense float4 stores (node-major).
    {
        int ni = t >> 2;           // 0..63 local node
        int qq = t & 3;            // batch quad
        int n  = n0 + ni;
        if (n < N_DIM) {
            const float* ef = reinterpret_cast<const float*>(s_e);
            const float* of = reinterpret_cast<const float*>(s_o);
            const float* af = reinterpret_cast<const float*>(s_a);
            int b0 = qq * 4;
            float4 ve = make_float4(ef[(b0+0)*68 + ni], ef[(b0+1)*68 + ni],
                                    ef[(b0+2)*68 + ni], ef[(b0+3)*68 + ni]);
            float4 vo = make_float4(of[(b0+0)*68 + ni], of[(b0+1)*68 + ni],
                                    of[(b0+2)*68 + ni], of[(b0+3)*68 + ni]);
            float4 va = make_float4(af[(b0+0)*68 + ni], af[(b0+1)*68 + ni],
                                    af[(b0+2)*68 + ni], af[(b0+3)*68 + ni]);
            int base = n * B_DIM + b0;
            *reinterpret_cast<float4*>(&g_ET [base]) = ve;
            *reinterpret_cast<float4*>(&g_OT [base]) = vo;
            *reinterpret_cast<float4*>(&g_ACC[base]) = va;
        }
    }
}

// ---------------------------------------------------------------------------
// Kernel B: edge scatter (R11 data path, plain launch; ~91% of LTS cap).
// 4 lanes per edge; each lane owns one batch quad (float4). Quad lanes load
// contiguous 16B pieces of the edge's 64B block (one 64B request per quad).
// red.global.add.v4.f32 -> no-return L2-side add, one RED.128 per lane.
// Signals programmatic completion so the PDL final kernel can ramp under
// our tail wave.
// ---------------------------------------------------------------------------
__global__ void __launch_bounds__(256)
edge_kernel(const float* __restrict__ w,
            const int*   __restrict__ src,
            const int*   __restrict__ dst)
{
    int t = blockIdx.x * blockDim.x + threadIdx.x;
    if (t < E_DIM * 4) {
        int e = t >> 2;
        int q = t & 3;

        int   s  = __ldg(&src[e]);
        int   d  = __ldg(&dst[e]);
        float wv = __ldg(&w[e]);

        const float4 Oj = __ldg(reinterpret_cast<const float4*>(&g_OT[s * B_DIM + q * 4]));
        const float4 En = __ldg(reinterpret_cast<const float4*>(&g_ET[d * B_DIM + q * 4]));

        float4 c;
        c.x = (Oj.x >= En.x) ? (Oj.x * wv) : (-Oj.x * wv);
        c.y = (Oj.y >= En.y) ? (Oj.y * wv) : (-Oj.y * wv);
        c.z = (Oj.z >= En.z) ? (Oj.z * wv) : (-Oj.z * wv);
        c.w = (Oj.w >= En.w) ? (Oj.w * wv) : (-Oj.w * wv);

        float* p = &g_ACC[d * B_DIM + q * 4];
        asm volatile("red.global.add.v4.f32 [%0], {%1, %2, %3, %4};"
                     :: "l"(p), "f"(c.x), "f"(c.y), "f"(c.z), "f"(c.w)
                     : "memory");
    }
    cudaTriggerProgrammaticLaunchCompletion();
}

// ---------------------------------------------------------------------------
// Kernel C: epilogue (R11 data path) with PDL: thr/dec prologue loads are
// independent of the edge kernel and issue before the dependency sync;
// ACC reads (which need all REDs) come after.
// ---------------------------------------------------------------------------
__global__ void __launch_bounds__(256)
final_kernel(const float* __restrict__ threshold,
             const float* __restrict__ decay,
             float* __restrict__ out)
{
    __shared__ float4 s_no[B_DIM][17];
    __shared__ float4 s_ne[B_DIM][17];

    const int n0 = blockIdx.x * 64;
    const int t  = threadIdx.x;

    int ni = t >> 2;
    int qq = t & 3;
    int n  = n0 + ni;
    float thr = 0.0f, dec = 0.0f;
    bool act = (n < N_DIM);
    if (act) {
        thr = __ldg(&threshold[n]);   // independent of the edge kernel
        dec = __ldg(&decay[n]);
    }

    cudaGridDependencySynchronize();   // wait for all REDs to be visible

    // Phase 1: dense loads + epilogue math.
    if (act) {
        int base = n * B_DIM + qq * 4;
        float4 Sv = *reinterpret_cast<const float4*>(&g_ACC[base]);
        float4 Ev = *reinterpret_cast<const float4*>(&g_ET [base]);

        float* nof = reinterpret_cast<float*>(s_no);
        float* nef = reinterpret_cast<float*>(s_ne);
        float Sa[4] = {Sv.x, Sv.y, Sv.z, Sv.w};
        float Ea[4] = {Ev.x, Ev.y, Ev.z, Ev.w};
        #pragma unroll
        for (int j = 0; j < 4; j++) {
            int b = qq * 4 + j;
            float S  = fminf(fmaxf(Sa[j], CLAMP_MIN_F), CLAMP_MAX_F);
            float ev = Ea[j];
            bool  gt    = S > thr;
            float new_o = fmaxf(S - thr, 0.0f);
            bool  mask  = (!gt) && (fabsf(S - ev) <= EPS_F);
            float new_e = gt ? new_o : (mask ? (ev - dec) : S);
            nof[b * 68 + ni] = new_o;
            nef[b * 68 + ni] = new_e;
        }
    }
    __syncthreads();

    // Phase 2: dense float4 stores (b-major).
    {
        int b  = t >> 4;           // 0..15
        int n4 = t & 15;           // node quad
        int nn = n0 + n4 * 4;
        if (nn < N_DIM) {
            *reinterpret_cast<float4*>(&out[b * N_DIM + nn])      = s_no[b][n4];
            *reinterpret_cast<float4*>(&out[BN + b * N_DIM + nn]) = s_ne[b][n4];
        }
    }
}

// ---------------------------------------------------------------------------
// Launch. Inputs (metadata order):
//   0 chem_influence (B,N) f32   1 E (B,N) f32       2 o_pre (B,N) f32
//   3 w (E,) f32                 4 threshold (N,) f32 5 decay (N,) f32
//   6 src (E,) i32               7 dst (E,) i32
// Output: new_o (B,N) then new_e (B,N) concatenated, f32.
// PDL only on edge->final: final's prologue+ramp hide under edge's tail;
// prep and edge are plain launches (no SM-slot contention on prep).
// ---------------------------------------------------------------------------
extern "C" void kernel_launch(void* const* d_in, const int* in_sizes, int n_in,
                              void* d_out, int out_size)
{
    const float* chem  = (const float*)d_in[0];
    const float* E     = (const float*)d_in[1];
    const float* o_pre = (const float*)d_in[2];
    const float* w     = (const float*)d_in[3];
    const float* thr   = (const float*)d_in[4];
    const float* dec   = (const float*)d_in[5];
    const int*   src   = (const int*)  d_in[6];
    const int*   dst   = (const int*)  d_in[7];
    float* out = (float*)d_out;

    int node_blocks = (N_DIM + 63) / 64;                // 782
    int edge_blocks = (E_DIM * 4 + 255) / 256;          // 25000

    prep_kernel<<<node_blocks, 256>>>(chem, E, o_pre);
    edge_kernel<<<edge_blocks, 256>>>(w, src, dst);

    cudaLaunchAttribute pdl[1];
    pdl[0].id = cudaLaunchAttributeProgrammaticStreamSerialization;
    pdl[0].val.programmaticStreamSerializationAllowed = 1;
    cudaLaunchConfig_t cfg = {};
    cfg.gridDim  = dim3(node_blocks, 1, 1);
    cfg.blockDim = dim3(256, 1, 1);
    cfg.attrs    = pdl;
    cfg.numAttrs = 1;
    cudaLaunchKernelEx(&cfg, final_kernel, thr, dec, out);
}